// round 1
// baseline (speedup 1.0000x reference)
#include <cuda_runtime.h>
#include <cstdint>
#include <math.h>

// Problem constants
#define BB 64
#define TT 512
#define DD 512
#define HH 1024
#define G4 4096   // 4*H

// ---------------- device scratch (no cudaMalloc allowed) ----------------
__device__ float g_xg[(size_t)BB * TT * G4];   // precomputed input projection + biases (512 MB)
__device__ float g_h[2][BB * HH];              // double-buffered hidden state
__device__ float g_c[BB * HH];                 // cell state (exclusive per-CTA ownership)

// ---------------- init: broadcast h0/c0 (makes graph replays deterministic) ----------------
__global__ void init_state(const float* __restrict__ h0, const float* __restrict__ c0) {
    int idx = blockIdx.x * blockDim.x + threadIdx.x;   // 0 .. B*H-1
    if (idx < BB * HH) {
        int k = idx & (HH - 1);
        g_h[0][idx] = h0[k];
        g_c[idx]    = c0[k];
    }
}

// ---------------- xg GEMM: XG[n][g] = sum_d x[n][d]*W_ih[g][d] + b_ih[g]+b_hh[g] ----------------
// M=32768, N=4096, K=512. BM=BN=128, BK=16, 256 threads, 8x8 micro-tile.
#define BM 128
#define BN 128
#define BK 16
__global__ __launch_bounds__(256, 2)
void xg_gemm(const float* __restrict__ X, const float* __restrict__ Wih,
             const float* __restrict__ bih, const float* __restrict__ bhh) {
    __shared__ float As[BK][BM + 4];
    __shared__ float Bs[BK][BN + 4];

    int tid = threadIdx.x;
    int bm = blockIdx.y;   // 0..255
    int bn = blockIdx.x;   // 0..31

    int trow = (tid / 16) * 8;   // 0..120
    int tcol = (tid % 16) * 8;   // 0..120

    const float* Aofs = X   + (size_t)bm * BM * DD;
    const float* Bofs = Wih + (size_t)bn * BN * DD;

    int a_r = tid >> 2;            // 0..63
    int a_c = (tid & 3) * 4;       // 0,4,8,12

    float acc[8][8];
#pragma unroll
    for (int i = 0; i < 8; i++)
#pragma unroll
        for (int j = 0; j < 8; j++) acc[i][j] = 0.f;

    for (int k0 = 0; k0 < DD; k0 += BK) {
#pragma unroll
        for (int i = 0; i < 2; i++) {
            float4 v = *(const float4*)(Aofs + (size_t)(a_r + i * 64) * DD + k0 + a_c);
            As[a_c + 0][a_r + i * 64] = v.x;
            As[a_c + 1][a_r + i * 64] = v.y;
            As[a_c + 2][a_r + i * 64] = v.z;
            As[a_c + 3][a_r + i * 64] = v.w;
        }
#pragma unroll
        for (int i = 0; i < 2; i++) {
            float4 v = *(const float4*)(Bofs + (size_t)(a_r + i * 64) * DD + k0 + a_c);
            Bs[a_c + 0][a_r + i * 64] = v.x;
            Bs[a_c + 1][a_r + i * 64] = v.y;
            Bs[a_c + 2][a_r + i * 64] = v.z;
            Bs[a_c + 3][a_r + i * 64] = v.w;
        }
        __syncthreads();
#pragma unroll
        for (int kk = 0; kk < BK; kk++) {
            float ar[8], br[8];
#pragma unroll
            for (int i = 0; i < 8; i++) ar[i] = As[kk][trow + i];
#pragma unroll
            for (int j = 0; j < 8; j++) br[j] = Bs[kk][tcol + j];
#pragma unroll
            for (int i = 0; i < 8; i++)
#pragma unroll
                for (int j = 0; j < 8; j++) acc[i][j] += ar[i] * br[j];
        }
        __syncthreads();
    }

    // epilogue: add biases, store
    float bias[8];
#pragma unroll
    for (int j = 0; j < 8; j++) {
        int g = bn * BN + tcol + j;
        bias[j] = bih[g] + bhh[g];
    }
#pragma unroll
    for (int i = 0; i < 8; i++) {
        size_t row = (size_t)(bm * BM + trow + i);
        float* op = g_xg + row * G4 + bn * BN + tcol;
#pragma unroll
        for (int j4 = 0; j4 < 8; j4 += 4) {
            float4 v;
            v.x = acc[i][j4 + 0] + bias[j4 + 0];
            v.y = acc[i][j4 + 1] + bias[j4 + 1];
            v.z = acc[i][j4 + 2] + bias[j4 + 2];
            v.w = acc[i][j4 + 3] + bias[j4 + 3];
            *(float4*)(op + j4) = v;
        }
    }
}

// ---------------- LSTM step ----------------
// 128 CTAs; CTA j owns hidden units [8j, 8j+8) for all 4 gates (32 gate cols).
// Active (mask!=0) rows compacted; gate GEMM over active rows only.
#define KC 128
#define WS_STRIDE 36
#define HS_STRIDE 66
// dynamic smem floats: Ws 1024*36 = 36864 | hs KC*66 = 8448 | gsm 8*8*33 = 2112
#define SMEM_FLOATS (36864 + 8448 + 2112)
#define SMEM_BYTES (SMEM_FLOATS * 4)

__device__ __forceinline__ float sigm(float x) { return 1.f / (1.f + expf(-x)); }

__global__ __launch_bounds__(256, 1)
void lstm_step(const float* __restrict__ Whh, const int* __restrict__ mask,
               float* __restrict__ out, int t) {
    extern __shared__ float sm[];
    float* Ws  = sm;                    // [1024][36] : Ws[k][col]
    float* hs  = sm + 1024 * WS_STRIDE; // [KC][66]   : hs[kk][r] (r = compacted active row)
    float* gsm = hs + KC * HS_STRIDE;   // per-warp [8][33] gate stash

    __shared__ int act[BB], inact[BB], counts[2], msh[BB];

    const float* hcur = g_h[t & 1];
    float*       hnext = g_h[(t + 1) & 1];

    int tid = threadIdx.x;
    int base = blockIdx.x * 8;          // first hidden unit owned

    if (tid < BB) msh[tid] = mask[tid * TT + t];
    __syncthreads();
    if (tid == 0) {
        int na = 0, ni = 0;
        for (int b = 0; b < BB; b++) {
            if (msh[b]) act[na++] = b; else inact[ni++] = b;
        }
        counts[0] = na; counts[1] = ni;
    }
    __syncthreads();
    int nact = counts[0], ninact = counts[1];

    // inactive rows: pass-through h, write output
    for (int i = tid; i < ninact * 8; i += 256) {
        int r = i >> 3, u = i & 7;
        int b = inact[r];
        int idx = b * HH + base + u;
        float v = hcur[idx];
        hnext[idx] = v;
        out[((size_t)b * TT + t) * HH + base + u] = v;
    }

    // stage W slice into SMEM: Ws[k][col], col = gate*8+u
    for (int i = tid; i < 32 * 256; i += 256) {
        int col = i >> 8;                 // 0..31
        int k4 = (i & 255) * 4;
        int gate = col >> 3, u = col & 7;
        const float* wp = Whh + ((size_t)(gate * HH + base + u)) * HH + k4;
        float4 v = *(const float4*)wp;
        Ws[(k4 + 0) * WS_STRIDE + col] = v.x;
        Ws[(k4 + 1) * WS_STRIDE + col] = v.y;
        Ws[(k4 + 2) * WS_STRIDE + col] = v.z;
        Ws[(k4 + 3) * WS_STRIDE + col] = v.w;
    }

    int w = tid >> 5, lane = tid & 31;
    int q = lane >> 3, c = lane & 7;     // q: rowgrp (2 rows), c: colgrp (4 cols)
    int r0 = w * 8 + q * 2;              // warp w handles compacted rows [8w, 8w+8)
    bool wact = (w * 8 < nact);

    float acc[2][4] = {{0.f,0.f,0.f,0.f},{0.f,0.f,0.f,0.f}};

    for (int k0 = 0; k0 < HH; k0 += KC) {
        __syncthreads();
        // stage compacted h chunk: hs[kk][r] = h[act[r]][k0+kk]
        for (int i = tid; i < nact * (KC / 4); i += 256) {
            int r = i / (KC / 4);
            int k4 = (i % (KC / 4)) * 4;
            float4 v = *(const float4*)(hcur + act[r] * HH + k0 + k4);
            hs[(k4 + 0) * HS_STRIDE + r] = v.x;
            hs[(k4 + 1) * HS_STRIDE + r] = v.y;
            hs[(k4 + 2) * HS_STRIDE + r] = v.z;
            hs[(k4 + 3) * HS_STRIDE + r] = v.w;
        }
        __syncthreads();
        if (wact) {
            const float* wsp = Ws + (size_t)k0 * WS_STRIDE + c * 4;
            const float* hsp = hs + r0;
#pragma unroll 4
            for (int kk = 0; kk < KC; kk++) {
                float4 wv = *(const float4*)(wsp + kk * WS_STRIDE);
                float2 hv = *(const float2*)(hsp + kk * HS_STRIDE);
                acc[0][0] += hv.x * wv.x; acc[0][1] += hv.x * wv.y;
                acc[0][2] += hv.x * wv.z; acc[0][3] += hv.x * wv.w;
                acc[1][0] += hv.y * wv.x; acc[1][1] += hv.y * wv.y;
                acc[1][2] += hv.y * wv.z; acc[1][3] += hv.y * wv.w;
            }
        }
    }

    // epilogue: add xg, activations, c/h update
    float* gw = gsm + w * (8 * 33);
    if (wact) {
        int gate = c >> 1;
        int gg0 = gate * HH + base + (c & 1) * 4;   // global gate index of 4 cols
#pragma unroll
        for (int i = 0; i < 2; i++) {
            int r = r0 + i;
            if (r < nact) {
                int b = act[r];
                float4 xv = *(const float4*)(g_xg + ((size_t)b * TT + t) * G4 + gg0);
                int rl = q * 2 + i;
                gw[rl * 33 + c * 4 + 0] = acc[i][0] + xv.x;
                gw[rl * 33 + c * 4 + 1] = acc[i][1] + xv.y;
                gw[rl * 33 + c * 4 + 2] = acc[i][2] + xv.z;
                gw[rl * 33 + c * 4 + 3] = acc[i][3] + xv.w;
            }
        }
    }
    __syncwarp();
    if (wact) {
#pragma unroll
        for (int ee = 0; ee < 2; ee++) {
            int e = lane * 2 + ee;        // 0..63 -> (row, unit)
            int rl = e >> 3, u = e & 7;
            int r = w * 8 + rl;
            if (r < nact) {
                int b = act[r];
                float gi = gw[rl * 33 + u];
                float gf = gw[rl * 33 + 8 + u];
                float gG = gw[rl * 33 + 16 + u];
                float go = gw[rl * 33 + 24 + u];
                float iv = sigm(gi);
                float fv = sigm(gf);
                float gv = tanhf(gG);
                float ov = sigm(go);
                int idx = b * HH + base + u;
                float cn = fv * g_c[idx] + iv * gv;
                float hn = ov * tanhf(cn);
                g_c[idx] = cn;
                hnext[idx] = hn;
                out[((size_t)b * TT + t) * HH + base + u] = hn;
            }
        }
    }
}

// ---------------- launch ----------------
extern "C" void kernel_launch(void* const* d_in, const int* in_sizes, int n_in,
                              void* d_out, int out_size) {
    const float* x    = (const float*)d_in[0];
    const int*   mask = (const int*)  d_in[1];
    const float* Wih  = (const float*)d_in[2];
    const float* Whh  = (const float*)d_in[3];
    const float* bih  = (const float*)d_in[4];
    const float* bhh  = (const float*)d_in[5];
    const float* h0   = (const float*)d_in[6];
    const float* c0   = (const float*)d_in[7];
    float* out = (float*)d_out;

    cudaFuncSetAttribute(lstm_step, cudaFuncAttributeMaxDynamicSharedMemorySize, SMEM_BYTES);

    init_state<<<(BB * HH + 255) / 256, 256>>>(h0, c0);
    xg_gemm<<<dim3(G4 / BN, (BB * TT) / BM), 256>>>(x, Wih, bih, bhh);
    for (int t = 0; t < TT; t++) {
        lstm_step<<<128, 256, SMEM_BYTES>>>(Whh, mask, out, t);
    }
}

// round 2
// speedup vs baseline: 1.6320x; 1.6320x over previous
#include <cuda_runtime.h>
#include <cstdint>
#include <math.h>

// Problem constants
#define BB 64
#define TT 512
#define DD 512
#define HH 1024
#define G4 4096   // 4*H
#define NBLK 128

// ---------------- device scratch (no cudaMalloc allowed) ----------------
__device__ float g_xg[(size_t)BB * TT * G4];   // input projection + biases (512 MB)
__device__ float g_h[2][BB * HH];              // double-buffered hidden state
__device__ float g_c[BB * HH];                 // cell state (CTA-exclusive columns)
__device__ unsigned g_bar;                     // grid barrier counter (monotonic per run)

// ---------------- init ----------------
__global__ void init_state(const float* __restrict__ h0, const float* __restrict__ c0) {
    int idx = blockIdx.x * blockDim.x + threadIdx.x;
    if (idx == 0) g_bar = 0u;
    if (idx < BB * HH) {
        int k = idx & (HH - 1);
        g_h[0][idx] = h0[k];
        g_c[idx]    = c0[k];
    }
}

// ---------------- xg GEMM (unchanged from round 1) ----------------
#define BM 128
#define BN 128
#define BK 16
__global__ __launch_bounds__(256, 2)
void xg_gemm(const float* __restrict__ X, const float* __restrict__ Wih,
             const float* __restrict__ bih, const float* __restrict__ bhh) {
    __shared__ float As[BK][BM + 4];
    __shared__ float Bs[BK][BN + 4];

    int tid = threadIdx.x;
    int bm = blockIdx.y;
    int bn = blockIdx.x;

    int trow = (tid / 16) * 8;
    int tcol = (tid % 16) * 8;

    const float* Aofs = X   + (size_t)bm * BM * DD;
    const float* Bofs = Wih + (size_t)bn * BN * DD;

    int a_r = tid >> 2;
    int a_c = (tid & 3) * 4;

    float acc[8][8];
#pragma unroll
    for (int i = 0; i < 8; i++)
#pragma unroll
        for (int j = 0; j < 8; j++) acc[i][j] = 0.f;

    for (int k0 = 0; k0 < DD; k0 += BK) {
#pragma unroll
        for (int i = 0; i < 2; i++) {
            float4 v = *(const float4*)(Aofs + (size_t)(a_r + i * 64) * DD + k0 + a_c);
            As[a_c + 0][a_r + i * 64] = v.x;
            As[a_c + 1][a_r + i * 64] = v.y;
            As[a_c + 2][a_r + i * 64] = v.z;
            As[a_c + 3][a_r + i * 64] = v.w;
        }
#pragma unroll
        for (int i = 0; i < 2; i++) {
            float4 v = *(const float4*)(Bofs + (size_t)(a_r + i * 64) * DD + k0 + a_c);
            Bs[a_c + 0][a_r + i * 64] = v.x;
            Bs[a_c + 1][a_r + i * 64] = v.y;
            Bs[a_c + 2][a_r + i * 64] = v.z;
            Bs[a_c + 3][a_r + i * 64] = v.w;
        }
        __syncthreads();
#pragma unroll
        for (int kk = 0; kk < BK; kk++) {
            float ar[8], br[8];
#pragma unroll
            for (int i = 0; i < 8; i++) ar[i] = As[kk][trow + i];
#pragma unroll
            for (int j = 0; j < 8; j++) br[j] = Bs[kk][tcol + j];
#pragma unroll
            for (int i = 0; i < 8; i++)
#pragma unroll
                for (int j = 0; j < 8; j++) acc[i][j] += ar[i] * br[j];
        }
        __syncthreads();
    }

    float bias[8];
#pragma unroll
    for (int j = 0; j < 8; j++) {
        int g = bn * BN + tcol + j;
        bias[j] = bih[g] + bhh[g];
    }
#pragma unroll
    for (int i = 0; i < 8; i++) {
        size_t row = (size_t)(bm * BM + trow + i);
        float* op = g_xg + row * G4 + bn * BN + tcol;
#pragma unroll
        for (int j4 = 0; j4 < 8; j4 += 4) {
            float4 v;
            v.x = acc[i][j4 + 0] + bias[j4 + 0];
            v.y = acc[i][j4 + 1] + bias[j4 + 1];
            v.z = acc[i][j4 + 2] + bias[j4 + 2];
            v.w = acc[i][j4 + 3] + bias[j4 + 3];
            *(float4*)(op + j4) = v;
        }
    }
}

// ---------------- persistent LSTM recurrence ----------------
// 128 co-resident CTAs (1/SM). CTA j owns hidden units [8j,8j+8) -> 32 gate cols.
// W slice (1024x32 fp32, SMEM layout [k][col], stride 36) loaded ONCE.
// Per step: compact active rows, cp.async-double-buffered h chunks, FFMA GEMM,
// fused gate epilogue, global atomic barrier.
#define KC 128
#define WS_STRIDE 36
#define HROW 132          // hs row stride (floats): KC + pad, float4-aligned
// dynamic smem floats: Ws 1024*36=36864 | hs 2*64*132=16896 | gsm 8*8*33=2112
#define SMEM_FLOATS (36864 + 16896 + 2112)
#define SMEM_BYTES  (SMEM_FLOATS * 4)

__device__ __forceinline__ float sigm(float x) { return 1.f / (1.f + expf(-x)); }

__device__ __forceinline__ void cp16(void* sdst, const void* gsrc) {
    unsigned d = (unsigned)__cvta_generic_to_shared(sdst);
    asm volatile("cp.async.cg.shared.global [%0], [%1], 16;\n" :: "r"(d), "l"(gsrc));
}
__device__ __forceinline__ void cp_commit() {
    asm volatile("cp.async.commit_group;\n" ::: "memory");
}
__device__ __forceinline__ void cp_wait1() {
    asm volatile("cp.async.wait_group 1;\n" ::: "memory");
}
__device__ __forceinline__ void cp_wait0() {
    asm volatile("cp.async.wait_group 0;\n" ::: "memory");
}

__global__ __launch_bounds__(256, 1)
void lstm_persistent(const float* __restrict__ Whh, const int* __restrict__ mask,
                     float* __restrict__ out) {
    extern __shared__ float sm[];
    float* Ws  = sm;                       // [1024][36]
    float* hs  = sm + 1024 * WS_STRIDE;    // [2][64][HROW]  non-transposed: hs[buf][r][k]
    float* gsm = hs + 2 * 64 * HROW;       // per-warp [8][33] gate stash

    __shared__ int act[BB], inact[BB], counts[2], msh[BB];

    int tid  = threadIdx.x;
    int base = blockIdx.x * 8;             // first hidden unit owned by this CTA
    int w    = tid >> 5, lane = tid & 31;
    int q    = lane >> 3, c = lane & 7;    // q: row-pair group, c: 4-col group
    int r0   = w * 8 + q * 2;              // compacted row pair start

    // ---- load W slice once: Ws[k][col], col = gate*8 + u ----
    for (int i = tid; i < 32 * 256; i += 256) {
        int col = i >> 8;
        int k4  = (i & 255) * 4;
        int gate = col >> 3, u = col & 7;
        const float* wp = Whh + ((size_t)(gate * HH + base + u)) * HH + k4;
        float4 v = *(const float4*)wp;
        Ws[(k4 + 0) * WS_STRIDE + col] = v.x;
        Ws[(k4 + 1) * WS_STRIDE + col] = v.y;
        Ws[(k4 + 2) * WS_STRIDE + col] = v.z;
        Ws[(k4 + 3) * WS_STRIDE + col] = v.w;
    }
    __syncthreads();

    for (int t = 0; t < TT; t++) {
        const float* hcur  = g_h[t & 1];
        float*       hnext = g_h[(t + 1) & 1];

        // ---- mask load + compaction ----
        if (tid < BB) msh[tid] = mask[tid * TT + t];
        __syncthreads();
        if (tid == 0) {
            int na = 0, ni = 0;
            for (int b = 0; b < BB; b++) {
                if (msh[b]) act[na++] = b; else inact[ni++] = b;
            }
            counts[0] = na; counts[1] = ni;
        }
        __syncthreads();
        int nact = counts[0], ninact = counts[1];

        // ---- inactive rows: pass-through (L2-coherent loads: persistent kernel,
        //      L1 may hold stale lines from step t-2 on the same buffer) ----
        for (int i = tid; i < ninact * 8; i += 256) {
            int r = i >> 3, u = i & 7;
            int b = inact[r];
            int idx = b * HH + base + u;
            float v = __ldcg(hcur + idx);
            hnext[idx] = v;
            out[((size_t)b * TT + t) * HH + base + u] = v;
        }

        float acc[2][4] = {{0.f,0.f,0.f,0.f},{0.f,0.f,0.f,0.f}};
        bool wact = (w * 8 < nact);

        // ---- prologue: stage chunk 0 into buf 0 (cp.async, L1-bypass) ----
        for (int i = tid; i < nact * 32; i += 256) {
            int r = i >> 5, ks = i & 31;
            cp16(hs + (size_t)r * HROW + ks * 4,
                 hcur + (size_t)act[r] * HH + ks * 4);
        }
        cp_commit();

        // ---- main K loop: 8 chunks, double-buffered ----
        for (int ch = 0; ch < 8; ch++) {
            int nxt = ch + 1;
            if (nxt < 8) {
                float* dstb = hs + (size_t)(nxt & 1) * 64 * HROW;
                const float* srcb = hcur + nxt * KC;
                for (int i = tid; i < nact * 32; i += 256) {
                    int r = i >> 5, ks = i & 31;
                    cp16(dstb + (size_t)r * HROW + ks * 4,
                         srcb + (size_t)act[r] * HH + ks * 4);
                }
                cp_commit();
                cp_wait1();
            } else {
                cp_commit();
                cp_wait0();
            }
            __syncthreads();

            if (wact) {
                const float* wp = Ws + (size_t)(ch * KC) * WS_STRIDE + c * 4;
                const float* hp = hs + (size_t)(ch & 1) * 64 * HROW + (size_t)r0 * HROW;
#pragma unroll 4
                for (int kk = 0; kk < KC; kk++) {
                    float4 wv = *(const float4*)(wp + (size_t)kk * WS_STRIDE);
                    float h0 = hp[kk];
                    float h1 = hp[HROW + kk];
                    acc[0][0] += h0 * wv.x; acc[0][1] += h0 * wv.y;
                    acc[0][2] += h0 * wv.z; acc[0][3] += h0 * wv.w;
                    acc[1][0] += h1 * wv.x; acc[1][1] += h1 * wv.y;
                    acc[1][2] += h1 * wv.z; acc[1][3] += h1 * wv.w;
                }
            }
            __syncthreads();   // before next stage overwrites the buffer we just read
        }

        // ---- epilogue: add xg, activations, state update ----
        float* gw = gsm + w * (8 * 33);
        if (wact) {
            int gate = c >> 1;
            int gg0  = gate * HH + base + (c & 1) * 4;
#pragma unroll
            for (int i = 0; i < 2; i++) {
                int r = r0 + i;
                if (r < nact) {
                    int b = act[r];
                    float4 xv = *(const float4*)(g_xg + ((size_t)b * TT + t) * G4 + gg0);
                    int rl = q * 2 + i;
                    gw[rl * 33 + c * 4 + 0] = acc[i][0] + xv.x;
                    gw[rl * 33 + c * 4 + 1] = acc[i][1] + xv.y;
                    gw[rl * 33 + c * 4 + 2] = acc[i][2] + xv.z;
                    gw[rl * 33 + c * 4 + 3] = acc[i][3] + xv.w;
                }
            }
        }
        __syncwarp();
        if (wact) {
#pragma unroll
            for (int ee = 0; ee < 2; ee++) {
                int e = lane * 2 + ee;
                int rl = e >> 3, u = e & 7;
                int r = w * 8 + rl;
                if (r < nact) {
                    int b = act[r];
                    float gi = gw[rl * 33 + u];
                    float gf = gw[rl * 33 + 8 + u];
                    float gG = gw[rl * 33 + 16 + u];
                    float go = gw[rl * 33 + 24 + u];
                    float iv = sigm(gi);
                    float fv = sigm(gf);
                    float gv = tanhf(gG);
                    float ov = sigm(go);
                    int idx = b * HH + base + u;
                    float cn = fv * g_c[idx] + iv * gv;
                    float hn = ov * tanhf(cn);
                    g_c[idx] = cn;
                    hnext[idx] = hn;
                    out[((size_t)b * TT + t) * HH + base + u] = hn;
                }
            }
        }

        // ---- grid barrier (monotonic counter; all 128 CTAs co-resident) ----
        __syncthreads();
        if (tid == 0) {
            __threadfence();
            atomicAdd(&g_bar, 1u);
            unsigned want = (unsigned)(t + 1) * NBLK;
            while (*(volatile unsigned*)&g_bar < want) { __nanosleep(64); }
        }
        __syncthreads();
        __threadfence();
    }
}

// ---------------- launch ----------------
extern "C" void kernel_launch(void* const* d_in, const int* in_sizes, int n_in,
                              void* d_out, int out_size) {
    const float* x    = (const float*)d_in[0];
    const int*   mask = (const int*)  d_in[1];
    const float* Wih  = (const float*)d_in[2];
    const float* Whh  = (const float*)d_in[3];
    const float* bih  = (const float*)d_in[4];
    const float* bhh  = (const float*)d_in[5];
    const float* h0   = (const float*)d_in[6];
    const float* c0   = (const float*)d_in[7];
    float* out = (float*)d_out;

    cudaFuncSetAttribute(lstm_persistent, cudaFuncAttributeMaxDynamicSharedMemorySize, SMEM_BYTES);

    init_state<<<(BB * HH + 255) / 256, 256>>>(h0, c0);
    xg_gemm<<<dim3(G4 / BN, (BB * TT) / BM), 256>>>(x, Wih, bih, bhh);
    lstm_persistent<<<NBLK, 256, SMEM_BYTES>>>(Whh, mask, out);
}